// round 12
// baseline (speedup 1.0000x reference)
#include <cuda_runtime.h>
#include <cstdint>
#include <math.h>

#define KSTEPS 512
#define BATCH  64
#define NSTATE 128
#define NINPUT 32
#define HIDDEN 256
#define FIN    161

// ---- solver SMEM (floats) ----
#define OFF_TL0 0        // 144: my T half, buf0 (4 x [32|4pad])
#define OFF_TL1 144      // 144: buf1
#define OFF_TR0 288      // 144: peer T half, buf0 (bulk-written)
#define OFF_TR1 432      // 144: buf1
#define OFF_TSS 576      // 512: time grid
#define OFF_MB  1088     // 4 mbarriers (u64)
#define SOLVER_SMEM_FLOATS 1104
#define SOLVER_SMEM_BYTES  (SOLVER_SMEM_FLOATS * 4)

// ---- reconstruct SMEM (floats) ----
#define ROFF_W2  0           // 64*130 u128 = 33280 floats
#define ROFF_TSS 33280       // 512
#define RECON_SMEM_FLOATS 33792
#define RECON_SMEM_BYTES  (RECON_SMEM_FLOATS * 4)

__device__ __align__(16) float g_M[HIDDEN * HIDDEN];           // M = W1y @ W2
__device__ float g_c[HIDDEN];                                   // c = W1y @ b2
__device__ float g_P[(size_t)BATCH * KSTEPS * HIDDEN];          // P[b][i][r] = Wu @ u_i
__device__ __align__(16) float g_S[(size_t)BATCH * (KSTEPS - 1) * HIDDEN]; // prefix sums

__device__ __forceinline__ unsigned long long ffma2(unsigned long long a,
                                                    unsigned long long b,
                                                    unsigned long long c) {
    unsigned long long d;
    asm("fma.rn.f32x2 %0, %1, %2, %3;" : "=l"(d) : "l"(a), "l"(b), "l"(c));
    return d;
}
__device__ __forceinline__ float lo32(unsigned long long v) { return __uint_as_float((unsigned)v); }
__device__ __forceinline__ float hi32(unsigned long long v) { return __uint_as_float((unsigned)(v >> 32)); }
__device__ __forceinline__ unsigned long long pack2(float a, float b) {
    return (unsigned long long)__float_as_uint(a) | ((unsigned long long)__float_as_uint(b) << 32);
}
__device__ __forceinline__ float tanh_fast(float x) {
    float y;
    asm("tanh.approx.f32 %0, %1;" : "=f"(y) : "f"(x));
    return y;
}
__device__ __forceinline__ uint32_t smem_u32(const void* p) {
    uint32_t a;
    asm("{ .reg .u64 tmp; cvta.to.shared.u64 tmp, %1; cvt.u32.u64 %0, tmp; }"
        : "=r"(a) : "l"(p));
    return a;
}
__device__ __forceinline__ uint32_t mapa_u32(uint32_t addr, uint32_t rank) {
    uint32_t r;
    asm("mapa.shared::cluster.u32 %0, %1, %2;" : "=r"(r) : "r"(addr), "r"(rank));
    return r;
}
__device__ __forceinline__ void mbar_arm(uint32_t addr, uint32_t txbytes) {
    asm volatile("mbarrier.arrive.expect_tx.shared::cta.b64 _, [%0], %1;"
                 :: "r"(addr), "r"(txbytes) : "memory");
}
__device__ __forceinline__ void mbar_init(uint32_t addr, uint32_t cnt) {
    asm volatile("mbarrier.init.shared.b64 [%0], %1;" :: "r"(addr), "r"(cnt) : "memory");
}
// one bulk DSMEM copy local smem -> peer smem, tx-completing on the peer's mbarrier
__device__ __forceinline__ void bulk_to_peer(uint32_t dst_remote, uint32_t src_local,
                                             uint32_t bytes, uint32_t mbar_remote) {
    asm volatile("cp.async.bulk.shared::cluster.shared::cta.mbarrier::complete_tx::bytes "
                 "[%0], [%1], %2, [%3];"
                 :: "r"(dst_remote), "r"(src_local), "r"(bytes), "r"(mbar_remote) : "memory");
}

#define WAIT_MBAR(addr, ph) do {                                                 \
    uint32_t _d;                                                                 \
    asm volatile("{\n\t.reg .pred p;\n\t"                                        \
        "mbarrier.try_wait.parity.acquire.cluster.shared::cta.b64 p, [%1], %2;\n\t" \
        "selp.b32 %0, 1, 0, p;\n\t}"                                             \
        : "=r"(_d) : "r"(addr), "r"(ph) : "memory");                             \
    while (!_d) {                                                                \
        asm volatile("{\n\t.reg .pred p;\n\t"                                    \
            "mbarrier.try_wait.parity.acquire.cluster.shared::cta.b64 p, [%1], %2, 0x989680;\n\t" \
            "selp.b32 %0, 1, 0, p;\n\t}"                                         \
            : "=r"(_d) : "r"(addr), "r"(ph) : "memory");                         \
    }                                                                            \
} while (0)

// ---------------- precompute M = W1[:,1:129] @ W2, c = W1[:,1:129] @ b2 ----------------
__global__ void precompute_M(const float* __restrict__ W1,
                             const float* __restrict__ W2,
                             const float* __restrict__ b2)
{
    __shared__ float w1row[FIN];
    const int r = blockIdx.x;
    const int k = threadIdx.x;
    for (int j = k; j < FIN; j += blockDim.x) w1row[j] = W1[r * FIN + j];
    __syncthreads();
    float acc = 0.f;
#pragma unroll 8
    for (int i = 0; i < NSTATE; i++)
        acc = fmaf(w1row[1 + i], __ldg(&W2[i * HIDDEN + k]), acc);
    g_M[r * HIDDEN + k] = acc;
    if (k == 0) {
        float c = 0.f;
        for (int i = 0; i < NSTATE; i++) c = fmaf(w1row[1 + i], __ldg(&b2[i]), c);
        g_c[r] = c;
    }
}

// ---------------- precompute P[b][i][r] = Wu[r,:] . us[b][i][:] ----------------
__global__ void precompute_P(const float* __restrict__ W1,
                             const float* __restrict__ us)
{
    __shared__ float ush[64 * NINPUT];
    const int b = blockIdx.x;
    const int i0 = blockIdx.y * 64;
    const int r = threadIdx.x;
    float wu[NINPUT];
#pragma unroll
    for (int j = 0; j < NINPUT; j++) wu[j] = __ldg(&W1[r * FIN + 129 + j]);
    for (int idx = r; idx < 64 * NINPUT; idx += 256)
        ush[idx] = us[((size_t)b * KSTEPS + i0) * NINPUT + idx];
    __syncthreads();
    for (int ii = 0; ii < 64; ii++) {
        float acc = 0.f;
#pragma unroll
        for (int j = 0; j < NINPUT; j++) acc = fmaf(wu[j], ush[ii * NINPUT + j], acc);
        g_P[((size_t)b * KSTEPS + i0 + ii) * HIDDEN + r] = acc;
    }
}

// ---------------- main solver: 2-CTA cluster, bulk exchange, no output phase ----------------
__global__ __launch_bounds__(512, 1) __cluster_dims__(2, 1, 1)
void ode_tsit5_kernel(const float* __restrict__ ts,
                      const float* __restrict__ y0,
                      const float* __restrict__ W1,
                      const float* __restrict__ b1)
{
    const float TH[6] = {0.0f, 0.161f, 0.327f, 0.9f, 0.9800255409045097f, 1.0f};
    const float A[5][5] = {
        {0.161f, 0.f, 0.f, 0.f, 0.f},
        {-0.008480655492356989f, 0.335480655492357f, 0.f, 0.f, 0.f},
        {2.8971530571054935f, -6.359448489975075f, 4.3622954328695815f, 0.f, 0.f},
        {5.325864828439257f, -11.748883564062828f, 7.4955393428898365f, -0.09249506636175525f, 0.f},
        {5.86145544294642f, -12.92096931784711f, 8.159367898576159f, -0.071584973281401f, -0.028269050394068383f}
    };
    const float Bw[6] = {0.09646076681806523f, 0.01f, 0.4798896504144996f,
                         1.379008574103742f, -3.290069515436081f, 2.324710524099774f};

    extern __shared__ float sm[];
    float* tss = sm + OFF_TSS;

    const int t = threadIdx.x;
    const int b = blockIdx.x >> 1;
    uint32_t rank;
    asm("mov.u32 %0, %%cluster_ctarank;" : "=r"(rank));
    const uint32_t prank = rank ^ 1u;

    const int rr = t >> 2;                     // local row (0..127)
    const int rg = (int)rank * 128 + rr;       // global pre-activation row
    const int q  = t & 3;                      // k-chunk

    // ---- cluster addresses ----
    const uint32_t smb  = smem_u32(sm);
    const uint32_t mb_l = smb + OFF_MB * 4;
    const uint32_t mb_r = mapa_u32(mb_l, prank);
    const uint32_t rtr0 = mapa_u32(smb + OFF_TR0 * 4, prank);
    const uint32_t rtr1 = mapa_u32(smb + OFF_TR1 * 4, prank);
    const uint32_t tl0a = smb + OFF_TL0 * 4;
    const uint32_t tl1a = smb + OFF_TL1 * 4;

    // T position for my row within the padded local buffer
    const int tpos = (rr >> 5) * 36 + (rr & 31);

    if (t == 0) {
#pragma unroll
        for (int m = 0; m < 4; m++) mbar_init(mb_l + m * 8, 1);   // armed via expect_tx
    }

    // ---- M row split: 32 local-half + 32 remote-half elems in registers ----
    unsigned long long mregL[16], mregR[16];
    {
        const unsigned long long* gmL =
            (const unsigned long long*)&g_M[rg * HIDDEN + (int)rank * 128 + q * 32];
        const unsigned long long* gmR =
            (const unsigned long long*)&g_M[rg * HIDDEN + (int)prank * 128 + q * 32];
#pragma unroll
        for (int m = 0; m < 16; m++) { mregL[m] = gmL[m]; mregR[m] = gmR[m]; }
    }
    const float creg = g_c[rg];
    const float w1t  = __ldg(&W1[rg * FIN]);

    if (t < KSTEPS) tss[t] = ts[t];

    // ---- beta = W1y[rg,:] . y0 + b1[rg] ----
    float beta;
    {
        const float* w1p = W1 + rg * FIN + 1 + q * 32;
        const float* yp  = y0 + b * NSTATE + q * 32;
        float acc = 0.f;
#pragma unroll 8
        for (int ii = 0; ii < 32; ii++) acc = fmaf(__ldg(&w1p[ii]), __ldg(&yp[ii]), acc);
        acc += __shfl_xor_sync(0xFFFFFFFFu, acc, 1);
        acc += __shfl_xor_sync(0xFFFFFFFFu, acc, 2);
        beta = acc + __ldg(&b1[rg]);
    }

    // ---- P projections ----
    const float* gPb = g_P + (size_t)b * KSTEPS * HIDDEN + rg;
    float P0    = __ldg(&gPb[0]);
    float P1    = __ldg(&gPb[HIDDEN]);
    float Pnext = __ldg(&gPb[2 * HIDDEN]);

    __syncthreads();
    asm volatile("barrier.cluster.arrive.aligned;" ::: "memory");
    asm volatile("barrier.cluster.wait.aligned;" ::: "memory");

    float Q1 = __fdividef(P1 - P0, tss[1] - tss[0]);
    float Q0 = Q1;
    float act = fmaf(w1t, tss[0], beta + P0);
    float Garr[5];
    float Sacc = 0.f;                           // prefix sum of h*Tb for my row
    uint32_t es = 0;

    float* gSb = g_S + (size_t)b * (KSTEPS - 1) * HIDDEN + rg;

    for (int step = 0; step < KSTEPS - 1; ++step) {
        const float t0   = tss[step];
        const float hcur = tss[step + 1] - t0;
        float Tbacc = 0.f, bGacc = 0.f;

#pragma unroll
        for (int s = 0; s < 6; s++) {
            const uint32_t eidx = es & 3u;
            const uint32_t eph  = (es >> 2) & 1u;
            es++;
            float* TL = sm + ((s & 1) ? OFF_TL1 : OFF_TL0);
            float* TR = sm + ((s & 1) ? OFF_TR1 : OFF_TR0);
            const uint32_t tla = (s & 1) ? tl1a : tl0a;
            const uint32_t rtr = (s & 1) ? rtr1 : rtr0;

            float T = tanh_fast(act);
            Tbacc = fmaf(Bw[s], T, Tbacc);
            if (q == 0) TL[tpos] = T;
            if (t == 0) mbar_arm(mb_l + eidx * 8, 576u);
            __syncthreads();                              // all local T written
            if (t == 0) {
                asm volatile("fence.proxy.async.shared::cta;" ::: "memory");
                bulk_to_peer(rtr, tla, 576u, mb_r + eidx * 8);   // ONE bulk op
            }

            // ---- local-half chunk dot (overlaps bulk flight) ----
            unsigned long long a0 = 0ull, a1 = 0ull, a2 = 0ull, a3 = 0ull;
            {
                const ulonglong2* TqL = (const ulonglong2*)(TL + q * 36);
#pragma unroll
                for (int m = 0; m < 4; m++) {
                    ulonglong2 z0 = TqL[2 * m], z1 = TqL[2 * m + 1];
                    a0 = ffma2(mregL[4 * m + 0], z0.x, a0);
                    a1 = ffma2(mregL[4 * m + 1], z0.y, a1);
                    a2 = ffma2(mregL[4 * m + 2], z1.x, a2);
                    a3 = ffma2(mregL[4 * m + 3], z1.y, a3);
                }
            }
            // ---- wait for peer bulk, then remote chunk ----
            WAIT_MBAR(mb_l + eidx * 8, eph);
            {
                const ulonglong2* TqR = (const ulonglong2*)(TR + q * 36);
#pragma unroll
                for (int m = 0; m < 4; m++) {
                    ulonglong2 z0 = TqR[2 * m], z1 = TqR[2 * m + 1];
                    a0 = ffma2(mregR[4 * m + 0], z0.x, a0);
                    a1 = ffma2(mregR[4 * m + 1], z0.y, a1);
                    a2 = ffma2(mregR[4 * m + 2], z1.x, a2);
                    a3 = ffma2(mregR[4 * m + 3], z1.y, a3);
                }
            }
            float v = (lo32(a0) + hi32(a0)) + (lo32(a1) + hi32(a1))
                    + (lo32(a2) + hi32(a2)) + (lo32(a3) + hi32(a3));
            v += __shfl_xor_sync(0xFFFFFFFFu, v, 1);
            v += __shfl_xor_sync(0xFFFFFFFFu, v, 2);
            float G = v + creg;

            bGacc = fmaf(Bw[s], G, bGacc);
            if (s < 5) {
                Garr[s] = G;
                float th = TH[s + 1];
                float t2 = th * th, t3 = t2 * th;
                float h00 = 2.f * t3 - 3.f * t2 + 1.f;
                float h01 = -2.f * t3 + 3.f * t2;
                float h10 = t3 - 2.f * t2 + th;
                float h11 = t3 - t2;
                float herm = h00 * P0 + h01 * P1 + hcur * (h10 * Q0 + h11 * Q1);
                float asum = 0.f;
#pragma unroll
                for (int j = 0; j <= s; j++) asum = fmaf(A[s][j], Garr[j], asum);
                act = fmaf(w1t, fmaf(th, hcur, t0), beta + herm + hcur * asum);
            }
        }

        // ---- step epilogue: prefix-sum S, fire-and-forget store; rotate state ----
        if (q == 0) {
            Sacc = fmaf(hcur, Tbacc, Sacc);
            gSb[(size_t)step * HIDDEN] = Sacc;
        }
        beta = fmaf(hcur, bGacc, beta);
        P0 = P1; Q0 = Q1; P1 = Pnext;
        if (step + 2 < KSTEPS) {
            Q1 = __fdividef(P1 - P0, tss[step + 2] - tss[step + 1]);
            if (step + 3 < KSTEPS) Pnext = __ldg(&gPb[(size_t)(step + 3) * HIDDEN]);
        } else {
            Q1 = 0.f;
        }
        act = fmaf(w1t, tss[step + 1], beta + P0);
    }

    asm volatile("barrier.cluster.arrive.aligned;" ::: "memory");
    asm volatile("barrier.cluster.wait.aligned;" ::: "memory");
}

// ---------------- reconstruct: out[b][n] = y0 + W2 . S_n + b2*(t_n - t_0) ----------------
__global__ __launch_bounds__(512, 1)
void reconstruct_kernel(const float* __restrict__ ts,
                        const float* __restrict__ y0,
                        const float* __restrict__ W2,
                        const float* __restrict__ b2,
                        float* __restrict__ out)
{
    extern __shared__ float sm[];
    ulonglong2* w2q = (ulonglong2*)(sm + ROFF_W2);   // [j4*130 + i]
    float* tss = sm + ROFF_TSS;

    const int b = blockIdx.x;
    const int t = threadIdx.x;
    const int i = t >> 2;
    const int q = t & 3;

    {
        const float4* W2v = (const float4*)W2;       // [128][64] float4
        for (int idx = t; idx < 128 * 64; idx += 512) {
            int ii = idx >> 6, j4 = idx & 63;
            float4 w = W2v[ii * 64 + j4];
            ulonglong2 pk; pk.x = pack2(w.x, w.y); pk.y = pack2(w.z, w.w);
            w2q[j4 * 130 + ii] = pk;
        }
    }
    if (t < KSTEPS) tss[t] = ts[t];

    const float y0r = __ldg(&y0[b * NSTATE + i]);
    const float b2r = __ldg(&b2[i]);
    if (t < NSTATE)
        out[(size_t)b * KSTEPS * NSTATE + t] = y0[b * NSTATE + t];  // row 0 = y0
    __syncthreads();

    const float tstart = tss[0];
    const float* gSb = g_S + (size_t)b * (KSTEPS - 1) * HIDDEN;

    for (int step = 0; step < KSTEPS - 1; ++step) {
        const ulonglong2* Sq = (const ulonglong2*)(gSb + (size_t)step * HIDDEN);
        unsigned long long a0 = 0ull, a1 = 0ull;
#pragma unroll
        for (int m = 0; m < 16; m++) {
            int j4 = m * 4 + q;
            ulonglong2 w  = w2q[j4 * 130 + i];
            ulonglong2 sv = __ldg((const ulonglong2*)&Sq[j4]);
            a0 = ffma2(w.x, sv.x, a0);
            a1 = ffma2(w.y, sv.y, a1);
        }
        float v = (lo32(a0) + hi32(a0)) + (lo32(a1) + hi32(a1));
        v += __shfl_xor_sync(0xFFFFFFFFu, v, 1);
        v += __shfl_xor_sync(0xFFFFFFFFu, v, 2);
        if (q == 0) {
            float yv = y0r + v + b2r * (tss[step + 1] - tstart);
            out[((size_t)b * KSTEPS + step + 1) * NSTATE + i] = yv;
        }
    }
}

extern "C" void kernel_launch(void* const* d_in, const int* in_sizes, int n_in,
                              void* d_out, int out_size)
{
    const float *ts = nullptr, *y0 = nullptr, *us = nullptr;
    const float *W1 = nullptr, *b1 = nullptr, *W2 = nullptr, *b2 = nullptr;
    for (int i = 0; i < n_in; i++) {
        switch (in_sizes[i]) {
            case 512:      ts = (const float*)d_in[i]; break;
            case 8192:     y0 = (const float*)d_in[i]; break;
            case 1048576:  us = (const float*)d_in[i]; break;
            case 41216:    W1 = (const float*)d_in[i]; break;
            case 256:      b1 = (const float*)d_in[i]; break;
            case 32768:    W2 = (const float*)d_in[i]; break;
            case 128:      b2 = (const float*)d_in[i]; break;
            default: break;
        }
    }
    float* out = (float*)d_out;

    precompute_M<<<HIDDEN, HIDDEN>>>(W1, W2, b2);
    {
        dim3 g(BATCH, KSTEPS / 64);
        precompute_P<<<g, 256>>>(W1, us);
    }
    cudaFuncSetAttribute(ode_tsit5_kernel,
                         cudaFuncAttributeMaxDynamicSharedMemorySize, SOLVER_SMEM_BYTES);
    ode_tsit5_kernel<<<BATCH * 2, 512, SOLVER_SMEM_BYTES>>>(ts, y0, W1, b1);

    cudaFuncSetAttribute(reconstruct_kernel,
                         cudaFuncAttributeMaxDynamicSharedMemorySize, RECON_SMEM_BYTES);
    reconstruct_kernel<<<BATCH, 512, RECON_SMEM_BYTES>>>(ts, y0, W2, b2, out);
}

// round 15
// speedup vs baseline: 1.1117x; 1.1117x over previous
#include <cuda_runtime.h>
#include <cstdint>
#include <math.h>

#define KSTEPS 512
#define BATCH  64
#define NSTATE 128
#define NINPUT 32
#define HIDDEN 256
#define FIN    161

// ---- solver SMEM (floats) ----
#define OFF_TL0 0        // 144: my T half, buf0 (4 x [32|4pad])
#define OFF_TL1 144      // 144: buf1
#define OFF_TR0 288      // 144: peer T half, buf0 (bulk-written)
#define OFF_TR1 432      // 144: buf1
#define OFF_TSS 576      // 512: time grid
#define OFF_MB  1088     // 4 mbarriers (u64)
#define SOLVER_SMEM_FLOATS 1104
#define SOLVER_SMEM_BYTES  (SOLVER_SMEM_FLOATS * 4)

// ---- reconstruct SMEM (floats) ----
#define ROFF_W2  0           // 64*130 u128 = 33280 floats
#define ROFF_TSS 33280       // 512
#define RECON_SMEM_FLOATS 33792
#define RECON_SMEM_BYTES  (RECON_SMEM_FLOATS * 4)
#define RECON_CHUNKS 4
#define RECON_CHUNK  128     // steps per CTA (4*128 = 512 >= 511)

__device__ __align__(16) float g_M[HIDDEN * HIDDEN];           // M = W1y @ W2
__device__ float g_c[HIDDEN];                                   // c = W1y @ b2
__device__ float g_P[(size_t)BATCH * KSTEPS * HIDDEN];          // P[b][i][r] = Wu @ u_i
__device__ __align__(16) float g_S[(size_t)BATCH * (KSTEPS - 1) * HIDDEN]; // prefix sums

__device__ __forceinline__ unsigned long long ffma2(unsigned long long a,
                                                    unsigned long long b,
                                                    unsigned long long c) {
    unsigned long long d;
    asm("fma.rn.f32x2 %0, %1, %2, %3;" : "=l"(d) : "l"(a), "l"(b), "l"(c));
    return d;
}
__device__ __forceinline__ float lo32(unsigned long long v) { return __uint_as_float((unsigned)v); }
__device__ __forceinline__ float hi32(unsigned long long v) { return __uint_as_float((unsigned)(v >> 32)); }
__device__ __forceinline__ unsigned long long pack2(float a, float b) {
    return (unsigned long long)__float_as_uint(a) | ((unsigned long long)__float_as_uint(b) << 32);
}
__device__ __forceinline__ float tanh_fast(float x) {
    float y;
    asm("tanh.approx.f32 %0, %1;" : "=f"(y) : "f"(x));
    return y;
}
__device__ __forceinline__ uint32_t smem_u32(const void* p) {
    uint32_t a;
    asm("{ .reg .u64 tmp; cvta.to.shared.u64 tmp, %1; cvt.u32.u64 %0, tmp; }"
        : "=r"(a) : "l"(p));
    return a;
}
__device__ __forceinline__ uint32_t mapa_u32(uint32_t addr, uint32_t rank) {
    uint32_t r;
    asm("mapa.shared::cluster.u32 %0, %1, %2;" : "=r"(r) : "r"(addr), "r"(rank));
    return r;
}
__device__ __forceinline__ void mbar_arm(uint32_t addr, uint32_t txbytes) {
    asm volatile("mbarrier.arrive.expect_tx.shared::cta.b64 _, [%0], %1;"
                 :: "r"(addr), "r"(txbytes) : "memory");
}
__device__ __forceinline__ void mbar_init(uint32_t addr, uint32_t cnt) {
    asm volatile("mbarrier.init.shared.b64 [%0], %1;" :: "r"(addr), "r"(cnt) : "memory");
}
// one bulk DSMEM copy local smem -> peer smem, tx-completing on the peer's mbarrier
__device__ __forceinline__ void bulk_to_peer(uint32_t dst_remote, uint32_t src_local,
                                             uint32_t bytes, uint32_t mbar_remote) {
    asm volatile("cp.async.bulk.shared::cluster.shared::cta.mbarrier::complete_tx::bytes "
                 "[%0], [%1], %2, [%3];"
                 :: "r"(dst_remote), "r"(src_local), "r"(bytes), "r"(mbar_remote) : "memory");
}

#define WAIT_MBAR(addr, ph) do {                                                 \
    uint32_t _d;                                                                 \
    asm volatile("{\n\t.reg .pred p;\n\t"                                        \
        "mbarrier.try_wait.parity.acquire.cluster.shared::cta.b64 p, [%1], %2;\n\t" \
        "selp.b32 %0, 1, 0, p;\n\t}"                                             \
        : "=r"(_d) : "r"(addr), "r"(ph) : "memory");                             \
    while (!_d) {                                                                \
        asm volatile("{\n\t.reg .pred p;\n\t"                                    \
            "mbarrier.try_wait.parity.acquire.cluster.shared::cta.b64 p, [%1], %2, 0x989680;\n\t" \
            "selp.b32 %0, 1, 0, p;\n\t}"                                         \
            : "=r"(_d) : "r"(addr), "r"(ph) : "memory");                         \
    }                                                                            \
} while (0)

// ---------------- precompute M = W1[:,1:129] @ W2, c = W1[:,1:129] @ b2 ----------------
__global__ void precompute_M(const float* __restrict__ W1,
                             const float* __restrict__ W2,
                             const float* __restrict__ b2)
{
    __shared__ float w1row[FIN];
    const int r = blockIdx.x;
    const int k = threadIdx.x;
    for (int j = k; j < FIN; j += blockDim.x) w1row[j] = W1[r * FIN + j];
    __syncthreads();
    float acc = 0.f;
#pragma unroll 8
    for (int i = 0; i < NSTATE; i++)
        acc = fmaf(w1row[1 + i], __ldg(&W2[i * HIDDEN + k]), acc);
    g_M[r * HIDDEN + k] = acc;
    if (k == 0) {
        float c = 0.f;
        for (int i = 0; i < NSTATE; i++) c = fmaf(w1row[1 + i], __ldg(&b2[i]), c);
        g_c[r] = c;
    }
}

// ---------------- precompute P[b][i][r] = Wu[r,:] . us[b][i][:] ----------------
__global__ void precompute_P(const float* __restrict__ W1,
                             const float* __restrict__ us)
{
    __shared__ float ush[64 * NINPUT];
    const int b = blockIdx.x;
    const int i0 = blockIdx.y * 64;
    const int r = threadIdx.x;
    float wu[NINPUT];
#pragma unroll
    for (int j = 0; j < NINPUT; j++) wu[j] = __ldg(&W1[r * FIN + 129 + j]);
    for (int idx = r; idx < 64 * NINPUT; idx += 256)
        ush[idx] = us[((size_t)b * KSTEPS + i0) * NINPUT + idx];
    __syncthreads();
    for (int ii = 0; ii < 64; ii++) {
        float acc = 0.f;
#pragma unroll
        for (int j = 0; j < NINPUT; j++) acc = fmaf(wu[j], ush[ii * NINPUT + j], acc);
        g_P[((size_t)b * KSTEPS + i0 + ii) * HIDDEN + r] = acc;
    }
}

// ---------------- main solver: 2-CTA cluster, bulk exchange, no output phase ----------------
__global__ __launch_bounds__(512, 1) __cluster_dims__(2, 1, 1)
void ode_tsit5_kernel(const float* __restrict__ ts,
                      const float* __restrict__ y0,
                      const float* __restrict__ W1,
                      const float* __restrict__ b1)
{
    const float TH[6] = {0.0f, 0.161f, 0.327f, 0.9f, 0.9800255409045097f, 1.0f};
    const float A[5][5] = {
        {0.161f, 0.f, 0.f, 0.f, 0.f},
        {-0.008480655492356989f, 0.335480655492357f, 0.f, 0.f, 0.f},
        {2.8971530571054935f, -6.359448489975075f, 4.3622954328695815f, 0.f, 0.f},
        {5.325864828439257f, -11.748883564062828f, 7.4955393428898365f, -0.09249506636175525f, 0.f},
        {5.86145544294642f, -12.92096931784711f, 8.159367898576159f, -0.071584973281401f, -0.028269050394068383f}
    };
    const float Bw[6] = {0.09646076681806523f, 0.01f, 0.4798896504144996f,
                         1.379008574103742f, -3.290069515436081f, 2.324710524099774f};

    extern __shared__ float sm[];
    float* tss = sm + OFF_TSS;

    const int t = threadIdx.x;
    const int b = blockIdx.x >> 1;
    uint32_t rank;
    asm("mov.u32 %0, %%cluster_ctarank;" : "=r"(rank));
    const uint32_t prank = rank ^ 1u;

    const int rr = t >> 2;                     // local row (0..127)
    const int rg = (int)rank * 128 + rr;       // global pre-activation row
    const int q  = t & 3;                      // k-chunk

    // ---- cluster addresses ----
    const uint32_t smb  = smem_u32(sm);
    const uint32_t mb_l = smb + OFF_MB * 4;
    const uint32_t mb_r = mapa_u32(mb_l, prank);
    const uint32_t rtr0 = mapa_u32(smb + OFF_TR0 * 4, prank);
    const uint32_t rtr1 = mapa_u32(smb + OFF_TR1 * 4, prank);
    const uint32_t tl0a = smb + OFF_TL0 * 4;
    const uint32_t tl1a = smb + OFF_TL1 * 4;

    // T position for my row within the padded local buffer
    const int tpos = (rr >> 5) * 36 + (rr & 31);

    if (t == 0) {
#pragma unroll
        for (int m = 0; m < 4; m++) mbar_init(mb_l + m * 8, 1);   // armed via expect_tx
    }

    // ---- M row split: 32 local-half + 32 remote-half elems in registers ----
    unsigned long long mregL[16], mregR[16];
    {
        const unsigned long long* gmL =
            (const unsigned long long*)&g_M[rg * HIDDEN + (int)rank * 128 + q * 32];
        const unsigned long long* gmR =
            (const unsigned long long*)&g_M[rg * HIDDEN + (int)prank * 128 + q * 32];
#pragma unroll
        for (int m = 0; m < 16; m++) { mregL[m] = gmL[m]; mregR[m] = gmR[m]; }
    }
    const float creg = g_c[rg];
    const float w1t  = __ldg(&W1[rg * FIN]);

    if (t < KSTEPS) tss[t] = ts[t];

    // ---- beta = W1y[rg,:] . y0 + b1[rg] ----
    float beta;
    {
        const float* w1p = W1 + rg * FIN + 1 + q * 32;
        const float* yp  = y0 + b * NSTATE + q * 32;
        float acc = 0.f;
#pragma unroll 8
        for (int ii = 0; ii < 32; ii++) acc = fmaf(__ldg(&w1p[ii]), __ldg(&yp[ii]), acc);
        acc += __shfl_xor_sync(0xFFFFFFFFu, acc, 1);
        acc += __shfl_xor_sync(0xFFFFFFFFu, acc, 2);
        beta = acc + __ldg(&b1[rg]);
    }

    // ---- P projections ----
    const float* gPb = g_P + (size_t)b * KSTEPS * HIDDEN + rg;
    float P0    = __ldg(&gPb[0]);
    float P1    = __ldg(&gPb[HIDDEN]);
    float Pnext = __ldg(&gPb[2 * HIDDEN]);

    __syncthreads();
    asm volatile("barrier.cluster.arrive.aligned;" ::: "memory");
    asm volatile("barrier.cluster.wait.aligned;" ::: "memory");

    float Q1 = __fdividef(P1 - P0, tss[1] - tss[0]);
    float Q0 = Q1;
    float act = fmaf(w1t, tss[0], beta + P0);
    float Garr[5];
    float Sacc = 0.f;                           // prefix sum of h*Tb for my row
    uint32_t es = 0;

    float* gSb = g_S + (size_t)b * (KSTEPS - 1) * HIDDEN + rg;

    for (int step = 0; step < KSTEPS - 1; ++step) {
        const float t0   = tss[step];
        const float hcur = tss[step + 1] - t0;
        float Tbacc = 0.f, bGacc = 0.f;

#pragma unroll
        for (int s = 0; s < 6; s++) {
            const uint32_t eidx = es & 3u;
            const uint32_t eph  = (es >> 2) & 1u;
            es++;
            float* TL = sm + ((s & 1) ? OFF_TL1 : OFF_TL0);
            float* TR = sm + ((s & 1) ? OFF_TR1 : OFF_TR0);
            const uint32_t tla = (s & 1) ? tl1a : tl0a;
            const uint32_t rtr = (s & 1) ? rtr1 : rtr0;

            float T = tanh_fast(act);
            Tbacc = fmaf(Bw[s], T, Tbacc);
            if (q == 0) TL[tpos] = T;
            if (t == 0) mbar_arm(mb_l + eidx * 8, 576u);
            __syncthreads();                              // all local T written
            if (t == 0) {
                asm volatile("fence.proxy.async.shared::cta;" ::: "memory");
                bulk_to_peer(rtr, tla, 576u, mb_r + eidx * 8);   // ONE bulk op
            }

            // ---- local-half chunk dot (overlaps bulk flight) ----
            unsigned long long a0 = 0ull, a1 = 0ull, a2 = 0ull, a3 = 0ull;
            {
                const ulonglong2* TqL = (const ulonglong2*)(TL + q * 36);
#pragma unroll
                for (int m = 0; m < 4; m++) {
                    ulonglong2 z0 = TqL[2 * m], z1 = TqL[2 * m + 1];
                    a0 = ffma2(mregL[4 * m + 0], z0.x, a0);
                    a1 = ffma2(mregL[4 * m + 1], z0.y, a1);
                    a2 = ffma2(mregL[4 * m + 2], z1.x, a2);
                    a3 = ffma2(mregL[4 * m + 3], z1.y, a3);
                }
            }
            // ---- wait for peer bulk, then remote chunk ----
            WAIT_MBAR(mb_l + eidx * 8, eph);
            {
                const ulonglong2* TqR = (const ulonglong2*)(TR + q * 36);
#pragma unroll
                for (int m = 0; m < 4; m++) {
                    ulonglong2 z0 = TqR[2 * m], z1 = TqR[2 * m + 1];
                    a0 = ffma2(mregR[4 * m + 0], z0.x, a0);
                    a1 = ffma2(mregR[4 * m + 1], z0.y, a1);
                    a2 = ffma2(mregR[4 * m + 2], z1.x, a2);
                    a3 = ffma2(mregR[4 * m + 3], z1.y, a3);
                }
            }
            float v = (lo32(a0) + hi32(a0)) + (lo32(a1) + hi32(a1))
                    + (lo32(a2) + hi32(a2)) + (lo32(a3) + hi32(a3));
            v += __shfl_xor_sync(0xFFFFFFFFu, v, 1);
            v += __shfl_xor_sync(0xFFFFFFFFu, v, 2);
            float G = v + creg;

            bGacc = fmaf(Bw[s], G, bGacc);
            if (s < 5) {
                Garr[s] = G;
                float th = TH[s + 1];
                float t2 = th * th, t3 = t2 * th;
                float h00 = 2.f * t3 - 3.f * t2 + 1.f;
                float h01 = -2.f * t3 + 3.f * t2;
                float h10 = t3 - 2.f * t2 + th;
                float h11 = t3 - t2;
                float herm = h00 * P0 + h01 * P1 + hcur * (h10 * Q0 + h11 * Q1);
                float asum = 0.f;
#pragma unroll
                for (int j = 0; j <= s; j++) asum = fmaf(A[s][j], Garr[j], asum);
                act = fmaf(w1t, fmaf(th, hcur, t0), beta + herm + hcur * asum);
            }
        }

        // ---- step epilogue: prefix-sum S, fire-and-forget store; rotate state ----
        if (q == 0) {
            Sacc = fmaf(hcur, Tbacc, Sacc);
            gSb[(size_t)step * HIDDEN] = Sacc;
        }
        beta = fmaf(hcur, bGacc, beta);
        P0 = P1; Q0 = Q1; P1 = Pnext;
        if (step + 2 < KSTEPS) {
            Q1 = __fdividef(P1 - P0, tss[step + 2] - tss[step + 1]);
            if (step + 3 < KSTEPS) Pnext = __ldg(&gPb[(size_t)(step + 3) * HIDDEN]);
        } else {
            Q1 = 0.f;
        }
        act = fmaf(w1t, tss[step + 1], beta + P0);
    }

    asm volatile("barrier.cluster.arrive.aligned;" ::: "memory");
    asm volatile("barrier.cluster.wait.aligned;" ::: "memory");
}

// ------- reconstruct: out[b][n] = y0 + W2 . S_n + b2*(t_n - t_0), step-parallel -------
__global__ __launch_bounds__(512, 1)
void reconstruct_kernel(const float* __restrict__ ts,
                        const float* __restrict__ y0,
                        const float* __restrict__ W2,
                        const float* __restrict__ b2,
                        float* __restrict__ out)
{
    extern __shared__ float sm[];
    ulonglong2* w2q = (ulonglong2*)(sm + ROFF_W2);   // [j4*130 + i]
    float* tss = sm + ROFF_TSS;

    const int b = blockIdx.x;
    const int c = blockIdx.y;                        // step chunk
    const int t = threadIdx.x;
    const int i = t >> 2;
    const int q = t & 3;

    {
        const float4* W2v = (const float4*)W2;       // [128][64] float4
        for (int idx = t; idx < 128 * 64; idx += 512) {
            int ii = idx >> 6, j4 = idx & 63;
            float4 w = W2v[ii * 64 + j4];
            ulonglong2 pk; pk.x = pack2(w.x, w.y); pk.y = pack2(w.z, w.w);
            w2q[j4 * 130 + ii] = pk;
        }
    }
    if (t < KSTEPS) tss[t] = ts[t];

    const float y0r = __ldg(&y0[b * NSTATE + i]);
    const float b2r = __ldg(&b2[i]);
    if (c == 0 && t < NSTATE)
        out[(size_t)b * KSTEPS * NSTATE + t] = y0[b * NSTATE + t];  // row 0 = y0
    __syncthreads();

    const float tstart = tss[0];
    const float* gSb = g_S + (size_t)b * (KSTEPS - 1) * HIDDEN;

    const int step0 = c * RECON_CHUNK;
    const int send  = min(step0 + RECON_CHUNK, KSTEPS - 1);

    for (int step = step0; step < send; ++step) {
        const ulonglong2* Sq = (const ulonglong2*)(gSb + (size_t)step * HIDDEN);
        unsigned long long a0 = 0ull, a1 = 0ull;
#pragma unroll
        for (int m = 0; m < 16; m++) {
            int j4 = m * 4 + q;
            ulonglong2 w  = w2q[j4 * 130 + i];
            ulonglong2 sv = __ldg(&Sq[j4]);
            a0 = ffma2(w.x, sv.x, a0);
            a1 = ffma2(w.y, sv.y, a1);
        }
        float v = (lo32(a0) + hi32(a0)) + (lo32(a1) + hi32(a1));
        v += __shfl_xor_sync(0xFFFFFFFFu, v, 1);
        v += __shfl_xor_sync(0xFFFFFFFFu, v, 2);
        if (q == 0) {
            float yv = y0r + v + b2r * (tss[step + 1] - tstart);
            out[((size_t)b * KSTEPS + step + 1) * NSTATE + i] = yv;
        }
    }
}

extern "C" void kernel_launch(void* const* d_in, const int* in_sizes, int n_in,
                              void* d_out, int out_size)
{
    const float *ts = nullptr, *y0 = nullptr, *us = nullptr;
    const float *W1 = nullptr, *b1 = nullptr, *W2 = nullptr, *b2 = nullptr;
    for (int i = 0; i < n_in; i++) {
        switch (in_sizes[i]) {
            case 512:      ts = (const float*)d_in[i]; break;
            case 8192:     y0 = (const float*)d_in[i]; break;
            case 1048576:  us = (const float*)d_in[i]; break;
            case 41216:    W1 = (const float*)d_in[i]; break;
            case 256:      b1 = (const float*)d_in[i]; break;
            case 32768:    W2 = (const float*)d_in[i]; break;
            case 128:      b2 = (const float*)d_in[i]; break;
            default: break;
        }
    }
    float* out = (float*)d_out;

    precompute_M<<<HIDDEN, HIDDEN>>>(W1, W2, b2);
    {
        dim3 g(BATCH, KSTEPS / 64);
        precompute_P<<<g, 256>>>(W1, us);
    }
    cudaFuncSetAttribute(ode_tsit5_kernel,
                         cudaFuncAttributeMaxDynamicSharedMemorySize, SOLVER_SMEM_BYTES);
    ode_tsit5_kernel<<<BATCH * 2, 512, SOLVER_SMEM_BYTES>>>(ts, y0, W1, b1);

    cudaFuncSetAttribute(reconstruct_kernel,
                         cudaFuncAttributeMaxDynamicSharedMemorySize, RECON_SMEM_BYTES);
    {
        dim3 g(BATCH, RECON_CHUNKS);
        reconstruct_kernel<<<g, 512, RECON_SMEM_BYTES>>>(ts, y0, W2, b2, out);
    }
}